// round 7
// baseline (speedup 1.0000x reference)
#include <cuda_runtime.h>
#include <cstdint>

// PolicyEncoder gather-sum:
// out[n, :] = bias + w_state0[obs0[n]] + w_state1[obs1[n]] + w_act0[act0[n]] + w_act1[act1[n]]
// N = 262144 rows, D = 128 floats per row.
//
// R7 = R5 (best: persistent warps + 2-stage pipeline, 4 blocks/SM exact wave)
//      + L1 partitioning by cache-op:
//  - state-table gathers (77MB random, zero L1 reuse) and index loads use
//    __ldcg: cache in L2 only, DO NOT allocate in L1.
//  - act-table gathers (1MB working set, ~260x reuse per line per launch)
//    and bias use __ldg: L1-allocated. With the state stream no longer
//    flushing L1, act reads hit in L1 and stop consuming LTS bandwidth,
//    which is the measured binding resource (~13.8 TB/s = LTS cap).
//  - output stays __stcs (evict-first streaming store).

struct Idx { int i0, i1, i2, i3; };

__device__ __forceinline__ Idx load_idx(const int* __restrict__ o0,
                                        const int* __restrict__ o1,
                                        const int* __restrict__ a0,
                                        const int* __restrict__ a1, int r) {
    Idx x;
    x.i0 = __ldcg(o0 + r);   // L2-only: don't pollute L1
    x.i1 = __ldcg(o1 + r);
    x.i2 = __ldcg(a0 + r);
    x.i3 = __ldcg(a1 + r);
    return x;
}

__global__ void __launch_bounds__(256, 4)
policy_encoder_kernel(const int* __restrict__ obs0,
                      const int* __restrict__ obs1,
                      const int* __restrict__ act0,
                      const int* __restrict__ act1,
                      const float4* __restrict__ w0,   // [OBS0, 32] state, 51MB
                      const float4* __restrict__ w1,   // [OBS1, 32] state, 26MB
                      const float4* __restrict__ w2,   // [ACT0, 32] act, 512KB
                      const float4* __restrict__ w3,   // [ACT1, 32] act, 512KB
                      const float4* __restrict__ bias, // [32]
                      float4* __restrict__ out,        // [N, 32]
                      int n)
{
    const int lane   = threadIdx.x & 31;
    const int gw     = (int)((blockIdx.x * blockDim.x + threadIdx.x) >> 5);
    const int stride = (int)((gridDim.x * blockDim.x) >> 5);

    if (gw >= n) return;

    const float4 b = __ldg(bias + lane);   // L1-resident
    const int last = n - 1;

    // ---- prologue: row0 indices + gathers, row1 indices ----
    Idx ic = load_idx(obs0, obs1, act0, act1, gw);
    int r1 = gw + stride;
    Idx in_ = load_idx(obs0, obs1, act0, act1, r1 <= last ? r1 : last);

    float4 g0 = __ldcg(w0 + (size_t)ic.i0 * 32 + lane);  // state: L2-only
    float4 g1 = __ldcg(w1 + (size_t)ic.i1 * 32 + lane);  // state: L2-only
    float4 g2 = __ldg (w2 + (size_t)ic.i2 * 32 + lane);  // act: L1
    float4 g3 = __ldg (w3 + (size_t)ic.i3 * 32 + lane);  // act: L1

    // ---- steady state ----
    for (int r = gw; r <= last; r += stride) {
        // indices for row r + 2*stride (clamped at tail)
        int rnn = r + 2 * stride;
        Idx inn = load_idx(obs0, obs1, act0, act1, rnn <= last ? rnn : last);

        // gathers for row r + stride (indices arrived last iteration)
        float4 h0 = __ldcg(w0 + (size_t)in_.i0 * 32 + lane);
        float4 h1 = __ldcg(w1 + (size_t)in_.i1 * 32 + lane);
        float4 h2 = __ldg (w2 + (size_t)in_.i2 * 32 + lane);
        float4 h3 = __ldg (w3 + (size_t)in_.i3 * 32 + lane);

        // consume row r (gathers issued one iteration ago)
        float4 res;
        res.x = b.x + g0.x + g1.x + g2.x + g3.x;
        res.y = b.y + g0.y + g1.y + g2.y + g3.y;
        res.z = b.z + g0.z + g1.z + g2.z + g3.z;
        res.w = b.w + g0.w + g1.w + g2.w + g3.w;
        __stcs(out + (size_t)r * 32 + lane, res);

        // rotate pipeline registers
        g0 = h0; g1 = h1; g2 = h2; g3 = h3;
        in_ = inn;
    }
}

extern "C" void kernel_launch(void* const* d_in, const int* in_sizes, int n_in,
                              void* d_out, int out_size)
{
    const int*    obs0 = (const int*)d_in[0];
    const int*    obs1 = (const int*)d_in[1];
    const int*    act0 = (const int*)d_in[2];
    const int*    act1 = (const int*)d_in[3];
    const float4* w0   = (const float4*)d_in[4];
    const float4* w1   = (const float4*)d_in[5];
    const float4* w2   = (const float4*)d_in[6];
    const float4* w3   = (const float4*)d_in[7];
    const float4* bias = (const float4*)d_in[8];
    float4*       out  = (float4*)d_out;

    const int n = in_sizes[0];     // number of rows (N)
    const int threads = 256;       // 8 warps/block
    const int blocks  = 148 * 4;   // one exact wave at 4 blocks/SM

    policy_encoder_kernel<<<blocks, threads>>>(obs0, obs1, act0, act1,
                                               w0, w1, w2, w3, bias, out, n);
}